// round 7
// baseline (speedup 1.0000x reference)
#include <cuda_runtime.h>

namespace {

constexpr int KNN  = 32;   // K nearest neighbors
constexpr int IN2  = 64;   // 2K MLP input
constexpr int MID  = 32;   // hidden width of fc2
constexpr int HALF = 16;   // hidden units per thread (2 threads per element)

__device__ __forceinline__ float fast_tanh(float x) {
    float y;
    asm("tanh.approx.f32 %0, %1;" : "=f"(y) : "f"(x));
    return y;
}

// pack {x, x} into a 64-bit register for f32x2 ops
__device__ __forceinline__ unsigned long long pack2(float x) {
    unsigned long long r;
    asm("mov.b64 %0, {%1, %1};" : "=l"(r) : "f"(x));
    return r;
}

// d = a * b + d (two independent fp32 lanes)
__device__ __forceinline__ void ffma2(unsigned long long& d,
                                      unsigned long long a,
                                      unsigned long long b) {
    asm("fma.rn.f32x2 %0, %1, %2, %0;" : "+l"(d) : "l"(a), "l"(b));
}

__device__ __forceinline__ void unpack2(unsigned long long p, float& lo, float& hi) {
    asm("mov.b64 {%0, %1}, %2;" : "=f"(lo), "=f"(hi) : "l"(p));
}

__global__ __launch_bounds__(128) void meta_kernel(
    const int*   __restrict__ vals,
    const float* __restrict__ dist,
    const float* __restrict__ w1,   // [64,32]
    const float* __restrict__ b1,   // [32]
    const float* __restrict__ w2,   // [32,2]
    const float* __restrict__ b2,   // [2]
    const float* __restrict__ fw1,  // [2,4]
    const float* __restrict__ fb1,  // [4]
    const float* __restrict__ fw2,  // [4,1]
    const float* __restrict__ fb2,  // [1]
    float* __restrict__ out,        // [n,3]
    int n)
{
    __shared__ __align__(16) float s_w1[IN2 * MID];
    __shared__ __align__(16) float s_b1[MID];
    __shared__ __align__(16) float s_w2[MID * 2];

    {
        const int tid = threadIdx.x;
        for (int i = tid; i < IN2 * MID; i += blockDim.x) s_w1[i] = w1[i];
        if (tid < MID)     s_b1[tid] = b1[tid];
        if (tid < MID * 2) s_w2[tid] = w2[tid];
        __syncthreads();
    }

    const int gt   = blockIdx.x * blockDim.x + threadIdx.x;
    const int e    = gt >> 1;          // element index
    const int half = gt & 1;           // which 16 hidden units this thread owns
    if (e >= n) return;
    const int off  = half * HALF;

    // ---- issue vals LDGs first: DRAM latency hides behind phase A ----
    int v[KNN];
    {
        const int4* vp = reinterpret_cast<const int4*>(vals + (size_t)e * KNN);
        #pragma unroll
        for (int c = 0; c < KNN / 4; c++) {
            int4 t = vp[c];
            v[4*c+0] = t.x; v[4*c+1] = t.y; v[4*c+2] = t.z; v[4*c+3] = t.w;
        }
    }

    // ---- init packed accumulators with bias slice (8 x f32x2 = 16 units) ----
    unsigned long long h2[HALF / 2];
    {
        const ulonglong2* bp = reinterpret_cast<const ulonglong2*>(s_b1 + off);
        #pragma unroll
        for (int q = 0; q < HALF / 4; q++) {      // 4 x 16B loads? no: HALF/4 = 4 -> 4 loads of 16B = 64B ✔
            ulonglong2 t = bp[q];
            h2[2*q+0] = t.x;
            h2[2*q+1] = t.y;
        }
    }

    // ---- phase A: distances -> packed FMA into h2 ----
    {
        const float4* dp = reinterpret_cast<const float4*>(dist + (size_t)e * KNN);
        #pragma unroll
        for (int c = 0; c < KNN / 4; c++) {
            float4 d4 = dp[c];
            float xs[4] = {d4.x, d4.y, d4.z, d4.w};
            #pragma unroll
            for (int r = 0; r < 4; r++) {
                const unsigned long long xx = pack2(xs[r]);
                const ulonglong2* wr = reinterpret_cast<const ulonglong2*>(
                    s_w1 + (c * 4 + r) * MID + off);
                #pragma unroll
                for (int q = 0; q < HALF / 4; q++) {
                    ulonglong2 w = wr[q];
                    ffma2(h2[2*q+0], xx, w.x);
                    ffma2(h2[2*q+1], xx, w.y);
                }
            }
        }
    }

    // ---- phase B: label counts -> packed FMA into h2 ----
    {
        int cnt = 0;
        #pragma unroll
        for (int k = 0; k < KNN; k++) {
            bool dup = (v[k] == 0);
            #pragma unroll
            for (int j = 0; j < k; j++) dup = dup || (v[j] == v[k]);
            cnt += dup ? 0 : 1;
            const unsigned long long cc = pack2((float)cnt);
            const ulonglong2* wr = reinterpret_cast<const ulonglong2*>(
                s_w1 + (KNN + k) * MID + off);
            #pragma unroll
            for (int q = 0; q < HALF / 4; q++) {
                ulonglong2 w = wr[q];
                ffma2(h2[2*q+0], cc, w.x);
                ffma2(h2[2*q+1], cc, w.y);
            }
        }
    }

    // ---- fc2 layer 2: partial sums over this thread's 16 hidden units ----
    float p0 = 0.f, p1 = 0.f;
    #pragma unroll
    for (int q = 0; q < HALF / 2; q++) {
        float a, b;
        unpack2(h2[q], a, b);
        const float ta = fast_tanh(a);
        const float tb = fast_tanh(b);
        const int j = 2 * q;          // local unit index of 'a'; 'b' is j+1
        p0 = fmaf(ta, s_w2[2 * (off + j) + 0], p0);
        p1 = fmaf(ta, s_w2[2 * (off + j) + 1], p1);
        p0 = fmaf(tb, s_w2[2 * (off + j + 1) + 0], p0);
        p1 = fmaf(tb, s_w2[2 * (off + j + 1) + 1], p1);
    }
    p0 += __shfl_xor_sync(0xffffffffu, p0, 1);
    p1 += __shfl_xor_sync(0xffffffffu, p1, 1);

    // ---- fc1 + store (even thread of the pair only) ----
    if (half == 0) {
        const float o0 = p0 + b2[0];
        const float o1 = p1 + b2[1];
        float o2 = fb2[0];
        #pragma unroll
        for (int m = 0; m < 4; m++) {
            const float t = fast_tanh(fb1[m] + fmaf(o0, fw1[m], o1 * fw1[4 + m]));
            o2 = fmaf(t, fw2[m], o2);
        }
        out[3*e+0] = o0;
        out[3*e+1] = o1;
        out[3*e+2] = o2;
    }
}

} // anonymous namespace

extern "C" void kernel_launch(void* const* d_in, const int* in_sizes, int n_in,
                              void* d_out, int out_size) {
    const int*   vals = (const int*)  d_in[0];
    const float* dist = (const float*)d_in[1];
    const float* w1   = (const float*)d_in[2];
    const float* b1   = (const float*)d_in[3];
    const float* w2   = (const float*)d_in[4];
    const float* b2   = (const float*)d_in[5];
    const float* fw1  = (const float*)d_in[6];
    const float* fb1  = (const float*)d_in[7];
    const float* fw2  = (const float*)d_in[8];
    const float* fb2  = (const float*)d_in[9];
    float* out = (float*)d_out;

    const int n = in_sizes[0] / KNN;        // B*S elements
    const int total = 2 * n;                // 2 threads per element
    const int threads = 128;
    const int blocks = (total + threads - 1) / threads;
    meta_kernel<<<blocks, threads>>>(vals, dist, w1, b1, w2, b2,
                                     fw1, fb1, fw2, fb2, out, n);
}

// round 9
// speedup vs baseline: 1.6617x; 1.6617x over previous
#include <cuda_runtime.h>
#include <cstdint>

namespace {

constexpr int KNN  = 32;   // K nearest neighbors
constexpr int IN2  = 64;   // 2K MLP input
constexpr int MID  = 32;   // hidden width of fc2
constexpr int HALF = 16;   // hidden units per thread (2 threads per element)

__device__ __forceinline__ float fast_tanh(float x) {
    float y;
    asm("tanh.approx.f32 %0, %1;" : "=f"(y) : "f"(x));
    return y;
}

__global__ __launch_bounds__(128) void meta_kernel(
    const int*   __restrict__ vals,
    const float* __restrict__ dist,
    const float* __restrict__ w1,   // [64,32]
    const float* __restrict__ b1,   // [32]
    const float* __restrict__ w2,   // [32,2]
    const float* __restrict__ b2,   // [2]
    const float* __restrict__ fw1,  // [2,4]
    const float* __restrict__ fb1,  // [4]
    const float* __restrict__ fw2,  // [4,1]
    const float* __restrict__ fb2,  // [1]
    float* __restrict__ out,        // [n,3]
    int n)
{
    __shared__ __align__(16) float s_w1[IN2 * MID];
    __shared__ __align__(16) float s_b1[MID];
    __shared__ __align__(16) float s_w2[MID * 2];

    {
        const int tid = threadIdx.x;
        for (int i = tid; i < IN2 * MID; i += blockDim.x) s_w1[i] = w1[i];
        if (tid < MID)     s_b1[tid] = b1[tid];
        if (tid < MID * 2) s_w2[tid] = w2[tid];
        __syncthreads();
    }

    const int gt   = blockIdx.x * blockDim.x + threadIdx.x;
    const int e    = gt >> 1;          // element index
    const int half = gt & 1;           // which 16 hidden units this thread owns
    if (e >= n) return;
    const int off  = half * HALF;

    // ---- issue ALL global loads first; latency hides behind the count chain ----
    int v[KNN];
    {
        const int4* vp = reinterpret_cast<const int4*>(vals + (size_t)e * KNN);
        #pragma unroll
        for (int c = 0; c < KNN / 4; c++) {
            int4 t = vp[c];
            v[4*c+0] = t.x; v[4*c+1] = t.y; v[4*c+2] = t.z; v[4*c+3] = t.w;
        }
    }
    float xs[KNN];
    {
        const float4* dp = reinterpret_cast<const float4*>(dist + (size_t)e * KNN);
        #pragma unroll
        for (int c = 0; c < KNN / 4; c++) {
            float4 t = dp[c];
            xs[4*c+0] = t.x; xs[4*c+1] = t.y; xs[4*c+2] = t.z; xs[4*c+3] = t.w;
        }
    }

    // ---- label counts via 128-bit seen-bitmap (labels are in [0,100)) ----
    // flag_k = (v[k] != 0) && not seen in v[0..k-1]; cnt_k = running sum.
    float cf[KNN];
    {
        uint64_t seen_lo = 0ull, seen_hi = 0ull;
        int cnt = 0;
        #pragma unroll
        for (int k = 0; k < KNN; k++) {
            const int      val = v[k];
            const uint64_t m   = 1ull << (val & 63);
            const bool     hi  = val >= 64;
            const uint64_t w   = hi ? seen_hi : seen_lo;
            const bool isnew   = ((w & m) == 0ull) && (val != 0);
            if (hi) seen_hi |= m; else seen_lo |= m;
            cnt += isnew ? 1 : 0;
            cf[k] = (float)cnt;
        }
    }

    // ---- init accumulators with bias slice ----
    float h[HALF];
    #pragma unroll
    for (int j = 0; j < HALF / 4; j++) {
        float4 bb = *reinterpret_cast<const float4*>(s_b1 + off + 4 * j);
        h[4*j+0] = bb.x; h[4*j+1] = bb.y; h[4*j+2] = bb.z; h[4*j+3] = bb.w;
    }

    // ---- phase B: label-count features (rows 32..63) ----
    #pragma unroll
    for (int k = 0; k < KNN; k++) {
        const float cfk = cf[k];
        const float* wr = s_w1 + (KNN + k) * MID + off;
        #pragma unroll
        for (int j = 0; j < HALF / 4; j++) {
            float4 w = *reinterpret_cast<const float4*>(wr + 4 * j);
            h[4*j+0] = fmaf(cfk, w.x, h[4*j+0]);
            h[4*j+1] = fmaf(cfk, w.y, h[4*j+1]);
            h[4*j+2] = fmaf(cfk, w.z, h[4*j+2]);
            h[4*j+3] = fmaf(cfk, w.w, h[4*j+3]);
        }
    }

    // ---- phase A: distance features (rows 0..31) ----
    #pragma unroll
    for (int i = 0; i < KNN; i++) {
        const float xi = xs[i];
        const float* wr = s_w1 + i * MID + off;
        #pragma unroll
        for (int j = 0; j < HALF / 4; j++) {
            float4 w = *reinterpret_cast<const float4*>(wr + 4 * j);
            h[4*j+0] = fmaf(xi, w.x, h[4*j+0]);
            h[4*j+1] = fmaf(xi, w.y, h[4*j+1]);
            h[4*j+2] = fmaf(xi, w.z, h[4*j+2]);
            h[4*j+3] = fmaf(xi, w.w, h[4*j+3]);
        }
    }

    // ---- fc2 layer 2: partial sums over this thread's 16 hidden units ----
    float p0 = 0.f, p1 = 0.f;
    #pragma unroll
    for (int j = 0; j < HALF; j++) {
        const float t = fast_tanh(h[j]);
        p0 = fmaf(t, s_w2[2 * (off + j) + 0], p0);
        p1 = fmaf(t, s_w2[2 * (off + j) + 1], p1);
    }
    p0 += __shfl_xor_sync(0xffffffffu, p0, 1);
    p1 += __shfl_xor_sync(0xffffffffu, p1, 1);

    // ---- fc1 + store (even thread of the pair only) ----
    if (half == 0) {
        const float o0 = p0 + b2[0];
        const float o1 = p1 + b2[1];
        float o2 = fb2[0];
        #pragma unroll
        for (int m = 0; m < 4; m++) {
            const float t = fast_tanh(fb1[m] + fmaf(o0, fw1[m], o1 * fw1[4 + m]));
            o2 = fmaf(t, fw2[m], o2);
        }
        out[3*e+0] = o0;
        out[3*e+1] = o1;
        out[3*e+2] = o2;
    }
}

} // anonymous namespace

extern "C" void kernel_launch(void* const* d_in, const int* in_sizes, int n_in,
                              void* d_out, int out_size) {
    const int*   vals = (const int*)  d_in[0];
    const float* dist = (const float*)d_in[1];
    const float* w1   = (const float*)d_in[2];
    const float* b1   = (const float*)d_in[3];
    const float* w2   = (const float*)d_in[4];
    const float* b2   = (const float*)d_in[5];
    const float* fw1  = (const float*)d_in[6];
    const float* fb1  = (const float*)d_in[7];
    const float* fw2  = (const float*)d_in[8];
    const float* fb2  = (const float*)d_in[9];
    float* out = (float*)d_out;

    const int n = in_sizes[0] / KNN;        // B*S elements
    const int total = 2 * n;                // 2 threads per element
    const int threads = 128;
    const int blocks = (total + threads - 1) / threads;
    meta_kernel<<<blocks, threads>>>(vals, dist, w1, b1, w2, b2,
                                     fw1, fb1, fw2, fb2, out, n);
}